// round 11
// baseline (speedup 1.0000x reference)
#include <cuda_runtime.h>
#include <cstdint>
#include <cstddef>

// Problem constants
#define NM 4
#define NB 2048
#define ND 1024
#define NE 8
#define NO 1024
#define NC 2

#define DSPLIT 2            // K split across blocks (512 each)
#define KHALF 512
#define NCH 8               // chunks per K-half
#define KC 64               // K cols per chunk (8 k8-steps)
#define ASTR 66             // A smem row stride in float2 (even -> uint4 ok)
#define BSTR 25             // B smem row stride in float2
#define SM_AS_BYTES (128 * ASTR * 8)        // 67584
#define SM_BS_BYTES (64 * BSTR * 8)         // 12800
#define SM_TOTAL (SM_AS_BYTES + SM_BS_BYTES)

// Scratch (no allocations allowed)
__device__ float g_vtab[ND * NE * NC];          // [d][e*2+c] fp32
__device__ float g_bdot[NE * NC];
__device__ uint2 g_bw[ND * BSTR];               // W tf32 (hi,lo), [k][n], col 24 = 0
__device__ float g_part[DSPLIT * NM * NB * 24]; // partials [split][tok][24]

// tf32 split: hi = rna(f), lo = rna(f - hi)
__device__ __forceinline__ uint2 tf32_split(float f) {
    uint32_t hi, lo;
    asm("cvt.rna.tf32.f32 %0, %1;" : "=r"(hi) : "f"(f));
    float r = f - __uint_as_float(hi);
    asm("cvt.rna.tf32.f32 %0, %1;" : "=r"(lo) : "f"(r));
    return make_uint2(hi, lo);
}

// m16n8k8 tf32 MMA, canonical Ampere layout, D accumulates in place
#define MMA_TF32(d, a0, a1, a2, a3, b0, b1) \
    asm volatile("mma.sync.aligned.m16n8k8.row.col.f32.tf32.tf32.f32 " \
        "{%0,%1,%2,%3}, {%4,%5,%6,%7}, {%8,%9}, {%0,%1,%2,%3};" \
        : "+f"((d)[0]), "+f"((d)[1]), "+f"((d)[2]), "+f"((d)[3]) \
        : "r"(a0), "r"(a1), "r"(a2), "r"(a3), "r"(b0), "r"(b1))

// ---------------------------------------------------------------------------
// Pass A (proven, ~4.5us): V = expert_w @ head_w, + bdot fused.
// ---------------------------------------------------------------------------
__global__ void __launch_bounds__(256) build_vtab_kernel(
    const float* __restrict__ expert_w,
    const float* __restrict__ head_w,
    const float* __restrict__ expert_b)
{
    __shared__ float hw[NO * NC];
    for (int i = threadIdx.x; i < NO * NC; i += 256) hw[i] = head_w[i];
    __syncthreads();

    const int lane = threadIdx.x & 31;
    const int wid  = threadIdx.x >> 5;
    const int r    = (blockIdx.x << 3) + wid;

    const float4* row4 = (const float4*)(expert_w + ((size_t)r << 10));
    float4 w[8];
#pragma unroll
    for (int i = 0; i < 8; i++) w[i] = row4[i * 32 + lane];

    float a0 = 0.f, a1 = 0.f;
#pragma unroll
    for (int i = 0; i < 8; i++) {
        const float4* h = (const float4*)(hw + ((i * 128 + lane * 4) << 1));
        float4 h0 = h[0], h1 = h[1];
        a0 += w[i].x * h0.x + w[i].y * h0.z + w[i].z * h1.x + w[i].w * h1.z;
        a1 += w[i].x * h0.y + w[i].y * h0.w + w[i].z * h1.y + w[i].w * h1.w;
    }
#pragma unroll
    for (int off = 16; off; off >>= 1) {
        a0 += __shfl_down_sync(0xffffffffu, a0, off);
        a1 += __shfl_down_sync(0xffffffffu, a1, off);
    }
    if (lane == 0) {
        int e = r >> 10, d = r & 1023;
        g_vtab[(d << 4) + (e << 1) + 0] = a0;
        g_vtab[(d << 4) + (e << 1) + 1] = a1;
    }

    if (blockIdx.x < 8 && wid == 0) {
        int e = blockIdx.x;
        const float4* eb4 = ((const float4*)expert_b) + (e << 8);
        float b0 = 0.f, b1 = 0.f;
#pragma unroll
        for (int i = 0; i < 8; i++) {
            float4 bb = eb4[i * 32 + lane];
            const float4* h = (const float4*)(hw + ((i * 32 + lane) << 3));
            float4 h0 = h[0], h1 = h[1];
            b0 += bb.x * h0.x + bb.y * h0.z + bb.z * h1.x + bb.w * h1.z;
            b1 += bb.x * h0.y + bb.y * h0.w + bb.z * h1.y + bb.w * h1.w;
        }
#pragma unroll
        for (int off = 16; off; off >>= 1) {
            b0 += __shfl_down_sync(0xffffffffu, b0, off);
            b1 += __shfl_down_sync(0xffffffffu, b1, off);
        }
        if (lane == 0) { g_bdot[e * 2] = b0; g_bdot[e * 2 + 1] = b1; }
    }
}

// ---------------------------------------------------------------------------
// Pass B: W tf32 hi/lo image, [k][n] with BSTR stride. n<8 gate, 8..23 V,
// n==24 zero pad.
// ---------------------------------------------------------------------------
__global__ void __launch_bounds__(256) build_wprep_kernel(
    const float* __restrict__ gate_w)
{
    int idx = blockIdx.x * 256 + threadIdx.x;        // 0..25599
    if (idx >= ND * BSTR) return;
    int k = idx / BSTR, n = idx - k * BSTR;
    float w = 0.f;
    if (n < 8)       w = gate_w[(k << 3) + n];
    else if (n < 24) w = g_vtab[(k << 4) + (n - 8)];
    g_bw[idx] = (n < 24) ? tf32_split(w) : make_uint2(0u, 0u);
}

// ---------------------------------------------------------------------------
// Main pass: tensor-core tf32-split GEMM via mma.sync (sm_100-legal).
// 128 CTAs x 256 thr = token-group (32 b x 4 m = 128 tokens) x K-half.
// Warp w owns token rows 16w..16w+15 (row r: b = b0+(r>>2), m = r&3).
// Per chunk (64 K): stage X as (hi,lo) uint2 pairs + copy W slice, then
// 8 k-steps x 3 ntiles x 3 split-products of m16n8k8 MMAs.
// Partials (24/token) -> g_part; reduce_kernel finishes.
// ---------------------------------------------------------------------------
__global__ void __launch_bounds__(256) moe_tc_kernel(
    const float* __restrict__ x)
{
    extern __shared__ char smem[];
    uint2* As = (uint2*)smem;                         // [128][ASTR]
    uint2* Bs = (uint2*)(smem + SM_AS_BYTES);         // [64][BSTR]
    float* part = (float*)smem;                       // epilogue alias [128][25]

    const int tid  = threadIdx.x;
    const int tg   = blockIdx.x >> 1;                 // token group 0..63
    const int ds   = blockIdx.x & 1;                  // K-half
    const int b0   = tg << 5;                         // 32 b-values
    const int w    = tid >> 5;
    const int lane = tid & 31;
    const int g    = lane >> 2;                       // groupID
    const int t    = lane & 3;                        // threadID in group
    const int wrow = w << 4;

    float d[3][4];
#pragma unroll
    for (int nt = 0; nt < 3; nt++)
#pragma unroll
        for (int k = 0; k < 4; k++) d[nt][k] = 0.f;

    for (int ch = 0; ch < NCH; ch++) {
        const int kbase = ds * KHALF + ch * KC;
        __syncthreads();                              // smem reusable
        // ---- stage A: 128 rows x 64 cols fp32 -> tf32 (hi,lo) ----
#pragma unroll
        for (int i = 0; i < 8; i++) {
            int idx = tid + (i << 8);                 // 0..2047
            int r = idx >> 4, c4 = idx & 15;
            size_t grow = (size_t)(((r & 3) << 11) + b0 + (r >> 2));
            float4 v = *(const float4*)(x + grow * ND + kbase + (c4 << 2));
            uint2 s0 = tf32_split(v.x), s1 = tf32_split(v.y);
            uint2 s2 = tf32_split(v.z), s3 = tf32_split(v.w);
            uint4* dst = (uint4*)(As + r * ASTR + (c4 << 2));
            dst[0] = make_uint4(s0.x, s0.y, s1.x, s1.y);
            dst[1] = make_uint4(s2.x, s2.y, s3.x, s3.y);
        }
        // ---- stage B: copy W slice [64][BSTR] ----
        for (int i = tid; i < 64 * BSTR; i += 256)
            Bs[i] = g_bw[(size_t)kbase * BSTR + i];
        __syncthreads();

        // ---- 8 k-steps of m16n8k8 ----
#pragma unroll
        for (int ks = 0; ks < 8; ks++) {
            const int k0 = ks << 3;
            uint2 A0 = As[(wrow + g)     * ASTR + k0 + t];
            uint2 A1 = As[(wrow + g + 8) * ASTR + k0 + t];
            uint2 A2 = As[(wrow + g)     * ASTR + k0 + t + 4];
            uint2 A3 = As[(wrow + g + 8) * ASTR + k0 + t + 4];
#pragma unroll
            for (int nt = 0; nt < 3; nt++) {
                uint2 B0 = Bs[(k0 + t)     * BSTR + (nt << 3) + g];
                uint2 B1 = Bs[(k0 + t + 4) * BSTR + (nt << 3) + g];
                MMA_TF32(d[nt], A0.x, A1.x, A2.x, A3.x, B0.x, B1.x);  // hi*hi
                MMA_TF32(d[nt], A0.x, A1.x, A2.x, A3.x, B0.y, B1.y);  // hi*lo
                MMA_TF32(d[nt], A0.y, A1.y, A2.y, A3.y, B0.x, B1.x);  // lo*hi
            }
        }
    }

    // ---- epilogue: frags -> smem [128][25] -> g_part ----
    __syncthreads();
    {
        int r0 = wrow + g;
#pragma unroll
        for (int nt = 0; nt < 3; nt++) {
            int cc = (nt << 3) + (t << 1);
            part[r0 * 25 + cc]           = d[nt][0];
            part[r0 * 25 + cc + 1]       = d[nt][1];
            part[(r0 + 8) * 25 + cc]     = d[nt][2];
            part[(r0 + 8) * 25 + cc + 1] = d[nt][3];
        }
    }
    __syncthreads();

    if (tid < 128) {
        float c[24];
#pragma unroll
        for (int k = 0; k < 24; k++) c[k] = part[tid * 25 + k];
        int tok = ((tid & 3) << 11) + b0 + (tid >> 2);     // m*2048 + b
        float4* pp = (float4*)(g_part + ((size_t)ds * NM * NB + tok) * 24);
#pragma unroll
        for (int k = 0; k < 6; k++)
            pp[k] = make_float4(c[4 * k], c[4 * k + 1], c[4 * k + 2], c[4 * k + 3]);
    }
}

// ---------------------------------------------------------------------------
// Reduce (proven round-8): sum splits, gate winner, m-mean, head bias.
// ---------------------------------------------------------------------------
__global__ void __launch_bounds__(256) reduce_kernel(
    const float* __restrict__ gate_b,
    const float* __restrict__ head_b,
    float* __restrict__ out)
{
    const int gt = blockIdx.x * 256 + threadIdx.x;   // 0..8191
    const int b  = gt >> 2;
    const int m  = gt & 3;
    const int tok = (m << 11) + b;

    float c[24];
    {
        const float4* p0 = (const float4*)(g_part + (size_t)tok * 24);
#pragma unroll
        for (int k = 0; k < 6; k++) {
            float4 v = p0[k];
            c[4 * k] = v.x; c[4 * k + 1] = v.y; c[4 * k + 2] = v.z; c[4 * k + 3] = v.w;
        }
#pragma unroll
        for (int sp = 1; sp < DSPLIT; sp++) {
            const float4* pp = (const float4*)(g_part + ((size_t)sp * NM * NB + tok) * 24);
#pragma unroll
            for (int k = 0; k < 6; k++) {
                float4 v = pp[k];
                c[4 * k]     += v.x; c[4 * k + 1] += v.y;
                c[4 * k + 2] += v.z; c[4 * k + 3] += v.w;
            }
        }
    }

    float g[8];
#pragma unroll
    for (int e = 0; e < 8; e++) g[e] = c[e] + gate_b[e];
    int i1 = 0; float m1 = g[0];
#pragma unroll
    for (int e = 1; e < 8; e++) if (g[e] > m1) { m1 = g[e]; i1 = e; }
    int i2 = 0; float m2 = -3.402823466e38f;
#pragma unroll
    for (int e = 0; e < 8; e++) if (e != i1 && g[e] > m2) { m2 = g[e]; i2 = e; }
    int wwin = (i1 > i2) ? i1 : i2;

    float o0 = c[8 + (wwin << 1) + 0] + g_bdot[(wwin << 1) + 0];
    float o1 = c[8 + (wwin << 1) + 1] + g_bdot[(wwin << 1) + 1];

    o0 += __shfl_down_sync(0xffffffffu, o0, 2);
    o0 += __shfl_down_sync(0xffffffffu, o0, 1);
    o1 += __shfl_down_sync(0xffffffffu, o1, 2);
    o1 += __shfl_down_sync(0xffffffffu, o1, 1);

    if (m == 0) {
        out[(b << 1) + 0] = 0.25f * o0 + head_b[0];
        out[(b << 1) + 1] = 0.25f * o1 + head_b[1];
    }
}

// ---------------------------------------------------------------------------
extern "C" void kernel_launch(void* const* d_in, const int* in_sizes, int n_in,
                              void* d_out, int out_size)
{
    const float* x        = (const float*)d_in[0];
    const float* gate_w   = (const float*)d_in[1];
    const float* gate_b   = (const float*)d_in[2];
    const float* expert_w = (const float*)d_in[3];
    const float* expert_b = (const float*)d_in[4];
    const float* head_w   = (const float*)d_in[5];
    const float* head_b   = (const float*)d_in[6];
    float* out = (float*)d_out;

    cudaFuncSetAttribute(moe_tc_kernel,
                         cudaFuncAttributeMaxDynamicSharedMemorySize, SM_TOTAL);

    build_vtab_kernel<<<1024, 256>>>(expert_w, head_w, expert_b);
    build_wprep_kernel<<<(ND * BSTR + 255) / 256, 256>>>(gate_w);
    moe_tc_kernel<<<128, 256, SM_TOTAL>>>(x);
    reduce_kernel<<<32, 256>>>(gate_b, head_b, out);
}

// round 12
// speedup vs baseline: 1.2691x; 1.2691x over previous
#include <cuda_runtime.h>
#include <cstdint>
#include <cstddef>

// Problem constants
#define NM 4
#define NB 2048
#define ND 1024
#define NE 8
#define NO 1024
#define NC 2

#define DSPLIT 4            // K split across blocks (256 each)
#define KQ 256
#define NCH 4               // chunks per K-quarter
#define KC 64               // K cols per chunk (8 k8-steps)
#define ASTR 66             // A smem row stride in uint2
#define BSTR 25             // B smem row stride in uint2
#define SM_AS_BYTES (128 * ASTR * 8)        // 67584
#define SM_BS_BYTES (64 * BSTR * 8)         // 12800
#define SM_TOTAL (SM_AS_BYTES + SM_BS_BYTES)

// Scratch (no allocations allowed)
__device__ float g_vtab[ND * NE * NC];          // [d][e*2+c] fp32
__device__ float g_bdot[NE * NC];
__device__ uint2 g_bw[ND * BSTR];               // W tf32 (hi,lo), [k][n], col 24 = 0
__device__ float g_part[DSPLIT * NM * NB * 24]; // partials [split][tok][24]

// tf32 split: hi = rna(f), lo = rna(f - hi)
__device__ __forceinline__ uint2 tf32_split(float f) {
    uint32_t hi, lo;
    asm("cvt.rna.tf32.f32 %0, %1;" : "=r"(hi) : "f"(f));
    float r = f - __uint_as_float(hi);
    asm("cvt.rna.tf32.f32 %0, %1;" : "=r"(lo) : "f"(r));
    return make_uint2(hi, lo);
}

// m16n8k8 tf32 MMA, canonical Ampere layout, D accumulates in place
#define MMA_TF32(d, a0, a1, a2, a3, b0, b1) \
    asm volatile("mma.sync.aligned.m16n8k8.row.col.f32.tf32.tf32.f32 " \
        "{%0,%1,%2,%3}, {%4,%5,%6,%7}, {%8,%9}, {%0,%1,%2,%3};" \
        : "+f"((d)[0]), "+f"((d)[1]), "+f"((d)[2]), "+f"((d)[3]) \
        : "r"(a0), "r"(a1), "r"(a2), "r"(a3), "r"(b0), "r"(b1))

// ---------------------------------------------------------------------------
// Pass A (proven, ~4.5us): V = expert_w @ head_w, + bdot fused.
// ---------------------------------------------------------------------------
__global__ void __launch_bounds__(256) build_vtab_kernel(
    const float* __restrict__ expert_w,
    const float* __restrict__ head_w,
    const float* __restrict__ expert_b)
{
    __shared__ float hw[NO * NC];
    for (int i = threadIdx.x; i < NO * NC; i += 256) hw[i] = head_w[i];
    __syncthreads();

    const int lane = threadIdx.x & 31;
    const int wid  = threadIdx.x >> 5;
    const int r    = (blockIdx.x << 3) + wid;

    const float4* row4 = (const float4*)(expert_w + ((size_t)r << 10));
    float4 w[8];
#pragma unroll
    for (int i = 0; i < 8; i++) w[i] = row4[i * 32 + lane];

    float a0 = 0.f, a1 = 0.f;
#pragma unroll
    for (int i = 0; i < 8; i++) {
        const float4* h = (const float4*)(hw + ((i * 128 + lane * 4) << 1));
        float4 h0 = h[0], h1 = h[1];
        a0 += w[i].x * h0.x + w[i].y * h0.z + w[i].z * h1.x + w[i].w * h1.z;
        a1 += w[i].x * h0.y + w[i].y * h0.w + w[i].z * h1.y + w[i].w * h1.w;
    }
#pragma unroll
    for (int off = 16; off; off >>= 1) {
        a0 += __shfl_down_sync(0xffffffffu, a0, off);
        a1 += __shfl_down_sync(0xffffffffu, a1, off);
    }
    if (lane == 0) {
        int e = r >> 10, d = r & 1023;
        g_vtab[(d << 4) + (e << 1) + 0] = a0;
        g_vtab[(d << 4) + (e << 1) + 1] = a1;
    }

    if (blockIdx.x < 8 && wid == 0) {
        int e = blockIdx.x;
        const float4* eb4 = ((const float4*)expert_b) + (e << 8);
        float b0 = 0.f, b1 = 0.f;
#pragma unroll
        for (int i = 0; i < 8; i++) {
            float4 bb = eb4[i * 32 + lane];
            const float4* h = (const float4*)(hw + ((i * 32 + lane) << 3));
            float4 h0 = h[0], h1 = h[1];
            b0 += bb.x * h0.x + bb.y * h0.z + bb.z * h1.x + bb.w * h1.z;
            b1 += bb.x * h0.y + bb.y * h0.w + bb.z * h1.y + bb.w * h1.w;
        }
#pragma unroll
        for (int off = 16; off; off >>= 1) {
            b0 += __shfl_down_sync(0xffffffffu, b0, off);
            b1 += __shfl_down_sync(0xffffffffu, b1, off);
        }
        if (lane == 0) { g_bdot[e * 2] = b0; g_bdot[e * 2 + 1] = b1; }
    }
}

// ---------------------------------------------------------------------------
// Pass B: W tf32 hi/lo image, [k][n] with BSTR stride.
// ---------------------------------------------------------------------------
__global__ void __launch_bounds__(256) build_wprep_kernel(
    const float* __restrict__ gate_w)
{
    int idx = blockIdx.x * 256 + threadIdx.x;
    if (idx >= ND * BSTR) return;
    int k = idx / BSTR, n = idx - k * BSTR;
    float w = 0.f;
    if (n < 8)       w = gate_w[(k << 3) + n];
    else if (n < 24) w = g_vtab[(k << 4) + (n - 8)];
    g_bw[idx] = (n < 24) ? tf32_split(w) : make_uint2(0u, 0u);
}

// ---------------------------------------------------------------------------
// Main pass, round 12: same verified tf32-split mma.sync math; parallelism
// fixed. 256 CTAs (64 token-groups x 4 K-quarters) x 256 thr -> 2 CTAs/SM
// (16 warps, two barrier domains), register prefetch hides LDG across
// chunk boundaries.
// ---------------------------------------------------------------------------
__global__ void __launch_bounds__(256) moe_tc_kernel(
    const float* __restrict__ x)
{
    extern __shared__ char smem[];
    uint2* As = (uint2*)smem;                         // [128][ASTR]
    uint2* Bs = (uint2*)(smem + SM_AS_BYTES);         // [64][BSTR]
    float* part = (float*)smem;                       // epilogue alias [128][25]

    const int tid  = threadIdx.x;
    const int tg   = blockIdx.x >> 2;                 // token group 0..63
    const int ds   = blockIdx.x & 3;                  // K-quarter
    const int b0   = tg << 5;                         // 32 b-values
    const int w    = tid >> 5;
    const int lane = tid & 31;
    const int g    = lane >> 2;                       // groupID
    const int t    = lane & 3;                        // threadID in group
    const int wrow = w << 4;

    // fixed A-staging geometry per thread: 8 float4 across the 128x64 tile
    int arow[8], acol[8];
#pragma unroll
    for (int i = 0; i < 8; i++) {
        int idx = tid + (i << 8);
        arow[i] = idx >> 4;
        acol[i] = idx & 15;
    }
    const int kbase0 = ds * KQ;

    float d[3][4];
#pragma unroll
    for (int nt = 0; nt < 3; nt++)
#pragma unroll
        for (int k = 0; k < 4; k++) d[nt][k] = 0.f;

    // prologue: prefetch chunk 0 A into registers
    float4 v[8];
#pragma unroll
    for (int i = 0; i < 8; i++) {
        size_t grow = (size_t)(((arow[i] & 3) << 11) + b0 + (arow[i] >> 2));
        v[i] = *(const float4*)(x + grow * ND + kbase0 + (acol[i] << 2));
    }

    for (int ch = 0; ch < NCH; ch++) {
        const int kbase = kbase0 + ch * KC;
        __syncthreads();                              // smem reusable
        // ---- STS A from prefetched regs (tf32 split inline) ----
#pragma unroll
        for (int i = 0; i < 8; i++) {
            uint2 s0 = tf32_split(v[i].x), s1 = tf32_split(v[i].y);
            uint2 s2 = tf32_split(v[i].z), s3 = tf32_split(v[i].w);
            uint4* dst = (uint4*)(As + arow[i] * ASTR + (acol[i] << 2));
            dst[0] = make_uint4(s0.x, s0.y, s1.x, s1.y);
            dst[1] = make_uint4(s2.x, s2.y, s3.x, s3.y);
        }
        // ---- stage B slice [64][BSTR] ----
        for (int i = tid; i < 64 * BSTR; i += 256)
            Bs[i] = g_bw[(size_t)kbase * BSTR + i];
        __syncthreads();

        // ---- prefetch next chunk A (latency hides under MMA below) ----
        if (ch < NCH - 1) {
#pragma unroll
            for (int i = 0; i < 8; i++) {
                size_t grow = (size_t)(((arow[i] & 3) << 11) + b0 + (arow[i] >> 2));
                v[i] = *(const float4*)(x + grow * ND + kbase + KC + (acol[i] << 2));
            }
        }

        // ---- 8 k-steps of m16n8k8 (3 ntiles x 3 split products) ----
#pragma unroll
        for (int ks = 0; ks < 8; ks++) {
            const int k0 = ks << 3;
            uint2 A0 = As[(wrow + g)     * ASTR + k0 + t];
            uint2 A1 = As[(wrow + g + 8) * ASTR + k0 + t];
            uint2 A2 = As[(wrow + g)     * ASTR + k0 + t + 4];
            uint2 A3 = As[(wrow + g + 8) * ASTR + k0 + t + 4];
#pragma unroll
            for (int nt = 0; nt < 3; nt++) {
                uint2 B0 = Bs[(k0 + t)     * BSTR + (nt << 3) + g];
                uint2 B1 = Bs[(k0 + t + 4) * BSTR + (nt << 3) + g];
                MMA_TF32(d[nt], A0.x, A1.x, A2.x, A3.x, B0.x, B1.x);  // hi*hi
                MMA_TF32(d[nt], A0.x, A1.x, A2.x, A3.x, B0.y, B1.y);  // hi*lo
                MMA_TF32(d[nt], A0.y, A1.y, A2.y, A3.y, B0.x, B1.x);  // lo*hi
            }
        }
    }

    // ---- epilogue: frags -> smem [128][25] -> g_part ----
    __syncthreads();
    {
        int r0 = wrow + g;
#pragma unroll
        for (int nt = 0; nt < 3; nt++) {
            int cc = (nt << 3) + (t << 1);
            part[r0 * 25 + cc]           = d[nt][0];
            part[r0 * 25 + cc + 1]       = d[nt][1];
            part[(r0 + 8) * 25 + cc]     = d[nt][2];
            part[(r0 + 8) * 25 + cc + 1] = d[nt][3];
        }
    }
    __syncthreads();

    if (tid < 128) {
        float c[24];
#pragma unroll
        for (int k = 0; k < 24; k++) c[k] = part[tid * 25 + k];
        int tok = ((tid & 3) << 11) + b0 + (tid >> 2);     // m*2048 + b
        float4* pp = (float4*)(g_part + ((size_t)ds * NM * NB + tok) * 24);
#pragma unroll
        for (int k = 0; k < 6; k++)
            pp[k] = make_float4(c[4 * k], c[4 * k + 1], c[4 * k + 2], c[4 * k + 3]);
    }
}

// ---------------------------------------------------------------------------
// Reduce, round 12: 4 lanes per token (128 blocks x 256 = 32K threads).
// Lane sp loads split sp; shfl_xor folds splits; shfl_down folds modality.
// ---------------------------------------------------------------------------
__global__ void __launch_bounds__(256) reduce_kernel(
    const float* __restrict__ gate_b,
    const float* __restrict__ head_b,
    float* __restrict__ out)
{
    const int T    = blockIdx.x * 256 + threadIdx.x;   // 0..32767
    const int tokq = T >> 2;                           // token 0..8191
    const int sp   = T & 3;                            // split
    const int b    = tokq >> 2;
    const int m    = tokq & 3;
    const int tok  = (m << 11) + b;

    float c[24];
    {
        const float4* pp = (const float4*)(g_part + ((size_t)sp * NM * NB + tok) * 24);
#pragma unroll
        for (int k = 0; k < 6; k++) {
            float4 vv = pp[k];
            c[4 * k] = vv.x; c[4 * k + 1] = vv.y; c[4 * k + 2] = vv.z; c[4 * k + 3] = vv.w;
        }
    }
    // fold 4 splits (lanes 4q..4q+3 share a token)
#pragma unroll
    for (int k = 0; k < 24; k++) {
        c[k] += __shfl_xor_sync(0xffffffffu, c[k], 1);
        c[k] += __shfl_xor_sync(0xffffffffu, c[k], 2);
    }

    float g[8];
#pragma unroll
    for (int e = 0; e < 8; e++) g[e] = c[e] + gate_b[e];
    int i1 = 0; float m1 = g[0];
#pragma unroll
    for (int e = 1; e < 8; e++) if (g[e] > m1) { m1 = g[e]; i1 = e; }
    int i2 = 0; float m2 = -3.402823466e38f;
#pragma unroll
    for (int e = 0; e < 8; e++) if (e != i1 && g[e] > m2) { m2 = g[e]; i2 = e; }
    int wwin = (i1 > i2) ? i1 : i2;

    float o0 = c[8 + (wwin << 1) + 0] + g_bdot[(wwin << 1) + 0];
    float o1 = c[8 + (wwin << 1) + 1] + g_bdot[(wwin << 1) + 1];

    // modality mean: lanes 16k+j, token m = j>>2 -> fold strides 4 and 8
    o0 += __shfl_down_sync(0xffffffffu, o0, 4);
    o0 += __shfl_down_sync(0xffffffffu, o0, 8);
    o1 += __shfl_down_sync(0xffffffffu, o1, 4);
    o1 += __shfl_down_sync(0xffffffffu, o1, 8);

    if ((T & 15) == 0) {
        out[(b << 1) + 0] = 0.25f * o0 + head_b[0];
        out[(b << 1) + 1] = 0.25f * o1 + head_b[1];
    }
}

// ---------------------------------------------------------------------------
extern "C" void kernel_launch(void* const* d_in, const int* in_sizes, int n_in,
                              void* d_out, int out_size)
{
    const float* x        = (const float*)d_in[0];
    const float* gate_w   = (const float*)d_in[1];
    const float* gate_b   = (const float*)d_in[2];
    const float* expert_w = (const float*)d_in[3];
    const float* expert_b = (const float*)d_in[4];
    const float* head_w   = (const float*)d_in[5];
    const float* head_b   = (const float*)d_in[6];
    float* out = (float*)d_out;

    cudaFuncSetAttribute(moe_tc_kernel,
                         cudaFuncAttributeMaxDynamicSharedMemorySize, SM_TOTAL);

    build_vtab_kernel<<<1024, 256>>>(expert_w, head_w, expert_b);
    build_wprep_kernel<<<(ND * BSTR + 255) / 256, 256>>>(gate_w);
    moe_tc_kernel<<<256, 256, SM_TOTAL>>>(x);
    reduce_kernel<<<128, 256>>>(gate_b, head_b, out);
}

// round 15
// speedup vs baseline: 1.4026x; 1.1052x over previous
#include <cuda_runtime.h>
#include <cstdint>
#include <cstddef>

// Problem constants
#define NM 4
#define NB 2048
#define ND 1024
#define NE 8
#define NO 1024
#define NC 2

#define XSTR 258   // x-tile row stride (floats); 2-way read conflict max

// Scratch (no allocations allowed)
__device__ float g_vtab[ND * NE * NC];   // [d][e*2+c]  64 KB
__device__ float g_bdot[NE * NC];
__device__ int   g_win[NM * NB];         // winner per token, [block][q] layout

// packed f32x2 FMA (sm_100a+)
#define FMA_F32X2(acc, a, b) \
    asm("fma.rn.f32x2 %0, %1, %2, %0;" : "+l"(acc) : "l"(a), "l"(b))
#define BCAST_F32X2(dst, f) \
    asm("mov.b64 %0, {%1, %1};" : "=l"(dst) : "f"(f))
#define UNPACK_F32X2(lo, hi, in) \
    asm("mov.b64 {%0, %1}, %2;" : "=f"(lo), "=f"(hi) : "l"(in))

// ---------------------------------------------------------------------------
// Pass A (proven, ~4.2us): V = expert_w @ head_w, + bdot fused.
// ---------------------------------------------------------------------------
__global__ void __launch_bounds__(256) build_vtab_kernel(
    const float* __restrict__ expert_w,
    const float* __restrict__ head_w,
    const float* __restrict__ expert_b)
{
    __shared__ float hw[NO * NC];
    for (int i = threadIdx.x; i < NO * NC; i += 256) hw[i] = head_w[i];
    __syncthreads();

    const int lane = threadIdx.x & 31;
    const int wid  = threadIdx.x >> 5;
    const int r    = (blockIdx.x << 3) + wid;

    const float4* row4 = (const float4*)(expert_w + ((size_t)r << 10));
    float4 w[8];
#pragma unroll
    for (int i = 0; i < 8; i++) w[i] = row4[i * 32 + lane];

    float a0 = 0.f, a1 = 0.f;
#pragma unroll
    for (int i = 0; i < 8; i++) {
        const float4* h = (const float4*)(hw + ((i * 128 + lane * 4) << 1));
        float4 h0 = h[0], h1 = h[1];
        a0 += w[i].x * h0.x + w[i].y * h0.z + w[i].z * h1.x + w[i].w * h1.z;
        a1 += w[i].x * h0.y + w[i].y * h0.w + w[i].z * h1.y + w[i].w * h1.w;
    }
#pragma unroll
    for (int off = 16; off; off >>= 1) {
        a0 += __shfl_down_sync(0xffffffffu, a0, off);
        a1 += __shfl_down_sync(0xffffffffu, a1, off);
    }
    if (lane == 0) {
        int e = r >> 10, d = r & 1023;
        g_vtab[(d << 4) + (e << 1) + 0] = a0;
        g_vtab[(d << 4) + (e << 1) + 1] = a1;
    }

    if (blockIdx.x < 8 && wid == 0) {
        int e = blockIdx.x;
        const float4* eb4 = ((const float4*)expert_b) + (e << 8);
        float b0 = 0.f, b1 = 0.f;
#pragma unroll
        for (int i = 0; i < 8; i++) {
            float4 bb = eb4[i * 32 + lane];
            const float4* h = (const float4*)(hw + ((i * 32 + lane) << 3));
            float4 h0 = h[0], h1 = h[1];
            b0 += bb.x * h0.x + bb.y * h0.z + bb.z * h1.x + bb.w * h1.z;
            b1 += bb.x * h0.y + bb.y * h0.w + bb.z * h1.y + bb.w * h1.w;
        }
#pragma unroll
        for (int off = 16; off; off >>= 1) {
            b0 += __shfl_down_sync(0xffffffffu, b0, off);
            b1 += __shfl_down_sync(0xffffffffu, b1, off);
        }
        if (lane == 0) { g_bdot[e * 2] = b0; g_bdot[e * 2 + 1] = b1; }
    }
}

// ---------------------------------------------------------------------------
// Pass G: gate logits (8 cols) + winner per token. Round-5 skeleton, table
// is gate_w only (32 KB -> 2 blocks/SM). 128 blocks x 512 thr; block = 64
// tokens (16 b x 4 m); thread (s,t): s = tid>>5 d-slice, t token lane
// (A=t, B=t+32). 2 table LDS.128 per d feed 8 FFMA2 (2 tokens).
// ---------------------------------------------------------------------------
__global__ void __launch_bounds__(512) gate_kernel(
    const float* __restrict__ x,
    const float* __restrict__ gate_w,
    const float* __restrict__ gate_b)
{
    extern __shared__ float sm[];
    float* gt  = sm;                    // 8192 floats: [d][8]
    float* xs  = sm + 8192;             // 64*258 = 16512 floats
    float* red = xs;                    // alias after mainloop

    const int tid = threadIdx.x;
    const int b0  = blockIdx.x << 4;
    const int t   = tid & 31;
    const int s   = tid >> 5;           // 0..15

    {
        const float4* gsrc = (const float4*)gate_w;
        float4* gdst = (float4*)gt;
        for (int i = tid; i < 2048; i += 512) gdst[i] = gsrc[i];
    }

    unsigned long long gaA[4], gaB[4];
#pragma unroll
    for (int k = 0; k < 4; k++) { gaA[k] = 0ull; gaB[k] = 0ull; }

    for (int chunk = 0; chunk < 4; chunk++) {
        const int dc = chunk << 8;
        __syncthreads();                // xs reusable; table fill done (iter 0)
        for (int v = tid; v < 4096; v += 512) {
            int r = v >> 6, c4 = v & 63;
            int row = ((r & 3) << 11) + b0 + (r >> 2);   // m*2048 + b0 + brel
            float4 t4 = *(const float4*)(x + ((size_t)row << 10) + dc + (c4 << 2));
            float* dst = xs + r * XSTR + (c4 << 2);
            *(float2*)(dst)     = make_float2(t4.x, t4.y);
            *(float2*)(dst + 2) = make_float2(t4.z, t4.w);
        }
        __syncthreads();

        const float* xA = xs + t * XSTR + (s << 4);
        const float* xB = xA + 32 * XSTR;
        const int dg0 = dc + (s << 4);
#pragma unroll
        for (int j = 0; j < 16; j += 2) {
            float2 xa = *(const float2*)(xA + j);
            float2 xb = *(const float2*)(xB + j);
            unsigned long long a0, a1, bp0, bp1;
            BCAST_F32X2(a0, xa.x);  BCAST_F32X2(a1, xa.y);
            BCAST_F32X2(bp0, xb.x); BCAST_F32X2(bp1, xb.y);
            const int dg = dg0 + j;
            const ulonglong2* gp = (const ulonglong2*)(gt + (dg << 3));
            ulonglong2 g0 = gp[0], g1 = gp[1];   // d = dg   (8 floats)
            ulonglong2 g2 = gp[2], g3 = gp[3];   // d = dg+1
            FMA_F32X2(gaA[0], a0, g0.x); FMA_F32X2(gaA[1], a0, g0.y);
            FMA_F32X2(gaA[2], a0, g1.x); FMA_F32X2(gaA[3], a0, g1.y);
            FMA_F32X2(gaB[0], bp0, g0.x); FMA_F32X2(gaB[1], bp0, g0.y);
            FMA_F32X2(gaB[2], bp0, g1.x); FMA_F32X2(gaB[3], bp0, g1.y);
            FMA_F32X2(gaA[0], a1, g2.x); FMA_F32X2(gaA[1], a1, g2.y);
            FMA_F32X2(gaA[2], a1, g3.x); FMA_F32X2(gaA[3], a1, g3.y);
            FMA_F32X2(gaB[0], bp1, g2.x); FMA_F32X2(gaB[1], bp1, g2.y);
            FMA_F32X2(gaB[2], bp1, g3.x); FMA_F32X2(gaB[3], bp1, g3.y);
        }
    }

    // fold 16 slices -> winner
    __syncthreads();
    {
        float* rp = red + (s * 32 + t) * 17;
#pragma unroll
        for (int k = 0; k < 4; k++) UNPACK_F32X2(rp[2 * k],     rp[2 * k + 1],     gaA[k]);
#pragma unroll
        for (int k = 0; k < 4; k++) UNPACK_F32X2(rp[8 + 2 * k], rp[9 + 2 * k],     gaB[k]);
    }
    __syncthreads();

    if (tid < 64) {
        const int q   = tid;
        const int lt  = q & 31;
        const int off = (q >> 5) * 8;
        float c[8];
#pragma unroll
        for (int k = 0; k < 8; k++) c[k] = red[lt * 17 + off + k];
#pragma unroll
        for (int s2 = 1; s2 < 16; s2++) {
            const float* rp = red + (s2 * 32 + lt) * 17 + off;
#pragma unroll
            for (int k = 0; k < 8; k++) c[k] += rp[k];
        }
        float g[8];
#pragma unroll
        for (int e = 0; e < 8; e++) g[e] = c[e] + gate_b[e];
        int i1 = 0; float m1 = g[0];
#pragma unroll
        for (int e = 1; e < 8; e++) if (g[e] > m1) { m1 = g[e]; i1 = e; }
        int i2 = 0; float m2 = -3.402823466e38f;
#pragma unroll
        for (int e = 0; e < 8; e++) if (e != i1 && g[e] > m2) { m2 = g[e]; i2 = e; }
        g_win[(blockIdx.x << 6) + q] = (i1 > i2) ? i1 : i2;
    }
}

// ---------------------------------------------------------------------------
// Pass S: selected-expert output only. Per (token,d): 1 packed FFMA2 with
// V[d][2w..2w+1] gathered from a chunk-staged V slice (<=8 distinct 8-byte
// addrs per warp -> dedup). Smem 82 KB -> 2 blocks/SM. Writes final output
// (winner bias, modality mean, head bias) directly.
// ---------------------------------------------------------------------------
__global__ void __launch_bounds__(512) select_kernel(
    const float* __restrict__ x,
    const float* __restrict__ head_b,
    float* __restrict__ out)
{
    extern __shared__ float sm[];
    float* vt  = sm;                    // 4096 floats: V chunk [256 d][16]
    float* xs  = sm + 4096;             // 64*258 = 16512 floats
    float* red = sm;                    // alias after mainloop

    const int tid = threadIdx.x;
    const int b0  = blockIdx.x << 4;
    const int t   = tid & 31;
    const int s   = tid >> 5;           // 0..15

    // winners for this thread's two tokens (constant through the loop)
    const int wA = g_win[(blockIdx.x << 6) + t];
    const int wB = g_win[(blockIdx.x << 6) + t + 32];

    unsigned long long accA = 0ull, accB = 0ull;

    for (int chunk = 0; chunk < 4; chunk++) {
        const int dc = chunk << 8;
        __syncthreads();
        // stage x (verbatim pattern)
        for (int v = tid; v < 4096; v += 512) {
            int r = v >> 6, c4 = v & 63;
            int row = ((r & 3) << 11) + b0 + (r >> 2);
            float4 t4 = *(const float4*)(x + ((size_t)row << 10) + dc + (c4 << 2));
            float* dst = xs + r * XSTR + (c4 << 2);
            *(float2*)(dst)     = make_float2(t4.x, t4.y);
            *(float2*)(dst + 2) = make_float2(t4.z, t4.w);
        }
        // stage V chunk: 256 d x 16 floats = 1024 float4
        {
            const float4* vsrc = (const float4*)g_vtab;
            float4* vdst = (float4*)vt;
            for (int i = tid; i < 1024; i += 512) vdst[i] = vsrc[(dc << 2) + i];
        }
        __syncthreads();

        const float* xA = xs + t * XSTR + (s << 4);
        const float* xB = xA + 32 * XSTR;
        const int dl0 = s << 4;         // chunk-local d base
#pragma unroll
        for (int j = 0; j < 16; j += 2) {
            float2 xa = *(const float2*)(xA + j);
            float2 xb = *(const float2*)(xB + j);
            unsigned long long a0, a1, bp0, bp1;
            BCAST_F32X2(a0, xa.x);  BCAST_F32X2(a1, xa.y);
            BCAST_F32X2(bp0, xb.x); BCAST_F32X2(bp1, xb.y);
            const int dl = dl0 + j;
            unsigned long long vA0 = *(const unsigned long long*)(vt + (dl << 4)       + (wA << 1));
            unsigned long long vA1 = *(const unsigned long long*)(vt + ((dl + 1) << 4) + (wA << 1));
            unsigned long long vB0 = *(const unsigned long long*)(vt + (dl << 4)       + (wB << 1));
            unsigned long long vB1 = *(const unsigned long long*)(vt + ((dl + 1) << 4) + (wB << 1));
            FMA_F32X2(accA, a0, vA0);
            FMA_F32X2(accA, a1, vA1);
            FMA_F32X2(accB, bp0, vB0);
            FMA_F32X2(accB, bp1, vB1);
        }
    }

    // fold 16 slices, finish
    __syncthreads();
    {
        float* rp = red + (s * 32 + t) * 5;
        UNPACK_F32X2(rp[0], rp[1], accA);
        UNPACK_F32X2(rp[2], rp[3], accB);
    }
    __syncthreads();

    if (tid < 64) {
        const int q   = tid;
        const int lt  = q & 31;
        const int off = (q >> 5) * 2;
        float o0 = red[lt * 5 + off], o1 = red[lt * 5 + off + 1];
#pragma unroll
        for (int s2 = 1; s2 < 16; s2++) {
            const float* rp = red + (s2 * 32 + lt) * 5 + off;
            o0 += rp[0];
            o1 += rp[1];
        }
        const int w = g_win[(blockIdx.x << 6) + q];
        o0 += g_bdot[(w << 1) + 0];
        o1 += g_bdot[(w << 1) + 1];

        // modality mean: tokens q..q+3 share b, m = q&3 (consecutive lanes)
        o0 += __shfl_down_sync(0xffffffffu, o0, 2);
        o0 += __shfl_down_sync(0xffffffffu, o0, 1);
        o1 += __shfl_down_sync(0xffffffffu, o1, 2);
        o1 += __shfl_down_sync(0xffffffffu, o1, 1);

        if ((q & 3) == 0) {
            int b = b0 + (q >> 2);
            out[(b << 1) + 0] = 0.25f * o0 + head_b[0];
            out[(b << 1) + 1] = 0.25f * o1 + head_b[1];
        }
    }
}

// ---------------------------------------------------------------------------
extern "C" void kernel_launch(void* const* d_in, const int* in_sizes, int n_in,
                              void* d_out, int out_size)
{
    const float* x        = (const float*)d_in[0];
    const float* gate_w   = (const float*)d_in[1];
    const float* gate_b   = (const float*)d_in[2];
    const float* expert_w = (const float*)d_in[3];
    const float* expert_b = (const float*)d_in[4];
    const float* head_w   = (const float*)d_in[5];
    const float* head_b   = (const float*)d_in[6];
    float* out = (float*)d_out;

    const size_t SMEM_G = (8192 + 64 * XSTR) * sizeof(float);   // 98,816 B
    const size_t SMEM_S = (4096 + 64 * XSTR) * sizeof(float);   // 82,432 B
    cudaFuncSetAttribute(gate_kernel,
                         cudaFuncAttributeMaxDynamicSharedMemorySize, (int)SMEM_G);
    cudaFuncSetAttribute(select_kernel,
                         cudaFuncAttributeMaxDynamicSharedMemorySize, (int)SMEM_S);

    build_vtab_kernel<<<1024, 256>>>(expert_w, head_w, expert_b);
    gate_kernel<<<128, 512, SMEM_G>>>(x, gate_w, gate_b);
    select_kernel<<<128, 512, SMEM_S>>>(x, head_b, out);
}

// round 16
// speedup vs baseline: 1.6180x; 1.1536x over previous
#include <cuda_runtime.h>
#include <cstdint>
#include <cstddef>

// Problem constants
#define NM 4
#define NB 2048
#define ND 1024
#define NE 8
#define NO 1024
#define NC 2

#define NCH 8      // chunks of 128 d-columns
#define CHC 128
#define XSTR 130   // x-tile row stride (floats); mod 32 == 2 -> 2-way conflict max

// Scratch (no allocations allowed)
__device__ float g_vtab[ND * NE * NC];   // [d][e*2+c]  64 KB
__device__ float g_bdot[NE * NC];        // 16 floats

// packed f32x2 FMA (sm_100a+)
#define FMA_F32X2(acc, a, b) \
    asm("fma.rn.f32x2 %0, %1, %2, %0;" : "+l"(acc) : "l"(a), "l"(b))
#define BCAST_F32X2(dst, f) \
    asm("mov.b64 %0, {%1, %1};" : "=l"(dst) : "f"(f))
#define UNPACK_F32X2(lo, hi, in) \
    asm("mov.b64 {%0, %1}, %2;" : "=f"(lo), "=f"(hi) : "l"(in))

// ---------------------------------------------------------------------------
// Pass A (proven, ~4.2us timed / L2-hot): V = expert_w @ head_w, + bdot.
// ---------------------------------------------------------------------------
__global__ void __launch_bounds__(256) build_vtab_kernel(
    const float* __restrict__ expert_w,
    const float* __restrict__ head_w,
    const float* __restrict__ expert_b)
{
    __shared__ float hw[NO * NC];  // [o*2+c]
    for (int i = threadIdx.x; i < NO * NC; i += 256) hw[i] = head_w[i];
    __syncthreads();

    const int lane = threadIdx.x & 31;
    const int wid  = threadIdx.x >> 5;
    const int r    = (blockIdx.x << 3) + wid;          // row = e*1024 + d

    const float4* row4 = (const float4*)(expert_w + ((size_t)r << 10));
    float4 w[8];
#pragma unroll
    for (int i = 0; i < 8; i++) w[i] = row4[i * 32 + lane];

    float a0 = 0.f, a1 = 0.f;
#pragma unroll
    for (int i = 0; i < 8; i++) {
        const float4* h = (const float4*)(hw + ((i * 128 + lane * 4) << 1));
        float4 h0 = h[0], h1 = h[1];
        a0 += w[i].x * h0.x + w[i].y * h0.z + w[i].z * h1.x + w[i].w * h1.z;
        a1 += w[i].x * h0.y + w[i].y * h0.w + w[i].z * h1.y + w[i].w * h1.w;
    }
#pragma unroll
    for (int off = 16; off; off >>= 1) {
        a0 += __shfl_down_sync(0xffffffffu, a0, off);
        a1 += __shfl_down_sync(0xffffffffu, a1, off);
    }
    if (lane == 0) {
        int e = r >> 10, d = r & 1023;
        g_vtab[(d << 4) + (e << 1) + 0] = a0;
        g_vtab[(d << 4) + (e << 1) + 1] = a1;
    }

    if (blockIdx.x < 8 && wid == 0) {
        int e = blockIdx.x;
        const float4* eb4 = ((const float4*)expert_b) + (e << 8);
        float b0 = 0.f, b1 = 0.f;
#pragma unroll
        for (int i = 0; i < 8; i++) {
            float4 bb = eb4[i * 32 + lane];
            const float4* h = (const float4*)(hw + ((i * 32 + lane) << 3));
            float4 h0 = h[0], h1 = h[1];
            b0 += bb.x * h0.x + bb.y * h0.z + bb.z * h1.x + bb.w * h1.z;
            b1 += bb.x * h0.y + bb.y * h0.w + bb.z * h1.y + bb.w * h1.w;
        }
#pragma unroll
        for (int off = 16; off; off >>= 1) {
            b0 += __shfl_down_sync(0xffffffffu, b0, off);
            b1 += __shfl_down_sync(0xffffffffu, b1, off);
        }
        if (lane == 0) { g_bdot[e * 2] = b0; g_bdot[e * 2 + 1] = b1; }
    }
}

// ---------------------------------------------------------------------------
// Main fused pass, round 16: round-5 math UNCHANGED (2 tokens/thread, all-8
// candidates + gate in one x pass, 12 broadcast LDS.128 -> 48 FFMA2 per 2-d).
// Skeleton software-pipelined: register prefetch + double-buffered x tile,
// ONE barrier per chunk, STS never waits on a fresh LDG, next chunk's LDG
// overlaps compute. 8 chunks x 128 cols. Smem 164.9 KB (1 block/SM).
//
// Hazard proof: warp at STS(ch) into buf[ch&1] has passed barrier(ch-1) =>
// all warps finished compute(ch-2), the last readers of that buffer.
// ---------------------------------------------------------------------------
__global__ void __launch_bounds__(512) moe_main_kernel(
    const float* __restrict__ x,
    const float* __restrict__ gate_w,
    const float* __restrict__ gate_b,
    const float* __restrict__ head_b,
    float* __restrict__ out)
{
    extern __shared__ float sm[];
    float* gt  = sm;                    // 8192  floats: gate_w [d][e]
    float* vt  = sm + 8192;             // 16384 floats: V [d][e*2+c]
    float* xs0 = sm + 24576;            // 64*130 = 8320 floats
    float* xs1 = sm + 24576 + 8320;
    float* red = xs0;                   // aliased after mainloop (spans both)

    const int tid = threadIdx.x;
    const int b0  = blockIdx.x << 4;    // 16 b-values per block
    const int t   = tid & 31;           // token lane (A=t, B=t+32)
    const int s   = tid >> 5;           // d-slice 0..15 (warp-uniform)

    // fill broadcast tables (coalesced float4)
    {
        const float4* gsrc = (const float4*)gate_w;
        float4* gdst = (float4*)gt;
        for (int i = tid; i < 2048; i += 512) gdst[i] = gsrc[i];
        const float4* vsrc = (const float4*)g_vtab;
        float4* vdst = (float4*)vt;
        for (int i = tid; i < 4096; i += 512) vdst[i] = vsrc[i];
    }

    // fixed staging geometry: 4 float4 per thread per chunk (64 rows x 32 f4)
    int arow[4], ac4[4];
    const float* gp[4];
#pragma unroll
    for (int i = 0; i < 4; i++) {
        int idx = tid + (i << 9);       // 0..2047
        arow[i] = idx >> 5;             // row 0..63
        ac4[i]  = idx & 31;             // float4 col 0..31
        int row = ((arow[i] & 3) << 11) + b0 + (arow[i] >> 2);  // m*2048+b0+brel
        gp[i] = x + ((size_t)row << 10) + (ac4[i] << 2);
    }

    unsigned long long gaA[4], vaA[8], gaB[4], vaB[8];
#pragma unroll
    for (int k = 0; k < 4; k++) { gaA[k] = 0ull; gaB[k] = 0ull; }
#pragma unroll
    for (int k = 0; k < 8; k++) { vaA[k] = 0ull; vaB[k] = 0ull; }

    // prologue: prefetch chunk 0
    float4 pf[4];
#pragma unroll
    for (int i = 0; i < 4; i++) pf[i] = *(const float4*)(gp[i]);

    for (int ch = 0; ch < NCH; ch++) {
        float* buf = (ch & 1) ? xs1 : xs0;

        // STS prefetched chunk (no LDG wait)
#pragma unroll
        for (int i = 0; i < 4; i++) {
            float* dst = buf + arow[i] * XSTR + (ac4[i] << 2);
            *(float2*)(dst)     = make_float2(pf[i].x, pf[i].y);
            *(float2*)(dst + 2) = make_float2(pf[i].z, pf[i].w);
        }
        __syncthreads();    // buffer visible to all; prior compute on it done

        // prefetch next chunk (latency hides under compute below)
        if (ch < NCH - 1) {
#pragma unroll
            for (int i = 0; i < 4; i++)
                pf[i] = *(const float4*)(gp[i] + (ch + 1) * CHC);
        }

        const float* xA = buf + t * XSTR + (s << 3);
        const float* xB = xA + 32 * XSTR;
        const int dg0 = (ch << 7) + (s << 3);
#pragma unroll
        for (int j = 0; j < 8; j += 2) {
            float2 xa = *(const float2*)(xA + j);
            float2 xb = *(const float2*)(xB + j);
            unsigned long long a0, a1, bp0, bp1;
            BCAST_F32X2(a0, xa.x);  BCAST_F32X2(a1, xa.y);
            BCAST_F32X2(bp0, xb.x); BCAST_F32X2(bp1, xb.y);
            const int dg = dg0 + j;

            // gate table: elems dg, dg+1 -> 4 x LDS.128, feeds 16 FFMA2
            {
                const ulonglong2* gpp = (const ulonglong2*)(gt + (dg << 3));
                ulonglong2 g0 = gpp[0], g1 = gpp[1], g2 = gpp[2], g3 = gpp[3];
                FMA_F32X2(gaA[0], a0, g0.x); FMA_F32X2(gaA[1], a0, g0.y);
                FMA_F32X2(gaA[2], a0, g1.x); FMA_F32X2(gaA[3], a0, g1.y);
                FMA_F32X2(gaB[0], bp0, g0.x); FMA_F32X2(gaB[1], bp0, g0.y);
                FMA_F32X2(gaB[2], bp0, g1.x); FMA_F32X2(gaB[3], bp0, g1.y);
                FMA_F32X2(gaA[0], a1, g2.x); FMA_F32X2(gaA[1], a1, g2.y);
                FMA_F32X2(gaA[2], a1, g3.x); FMA_F32X2(gaA[3], a1, g3.y);
                FMA_F32X2(gaB[0], bp1, g2.x); FMA_F32X2(gaB[1], bp1, g2.y);
                FMA_F32X2(gaB[2], bp1, g3.x); FMA_F32X2(gaB[3], bp1, g3.y);
            }
            // V table elem dg: 4 x LDS.128, feeds 16 FFMA2
            {
                const ulonglong2* vp = (const ulonglong2*)(vt + (dg << 4));
                ulonglong2 v0 = vp[0], v1 = vp[1], v2 = vp[2], v3 = vp[3];
                FMA_F32X2(vaA[0], a0, v0.x); FMA_F32X2(vaA[1], a0, v0.y);
                FMA_F32X2(vaA[2], a0, v1.x); FMA_F32X2(vaA[3], a0, v1.y);
                FMA_F32X2(vaA[4], a0, v2.x); FMA_F32X2(vaA[5], a0, v2.y);
                FMA_F32X2(vaA[6], a0, v3.x); FMA_F32X2(vaA[7], a0, v3.y);
                FMA_F32X2(vaB[0], bp0, v0.x); FMA_F32X2(vaB[1], bp0, v0.y);
                FMA_F32X2(vaB[2], bp0, v1.x); FMA_F32X2(vaB[3], bp0, v1.y);
                FMA_F32X2(vaB[4], bp0, v2.x); FMA_F32X2(vaB[5], bp0, v2.y);
                FMA_F32X2(vaB[6], bp0, v3.x); FMA_F32X2(vaB[7], bp0, v3.y);
            }
            // V table elem dg+1: 4 x LDS.128, feeds 16 FFMA2
            {
                const ulonglong2* vp = (const ulonglong2*)(vt + ((dg + 1) << 4));
                ulonglong2 v4 = vp[0], v5 = vp[1], v6 = vp[2], v7 = vp[3];
                FMA_F32X2(vaA[0], a1, v4.x); FMA_F32X2(vaA[1], a1, v4.y);
                FMA_F32X2(vaA[2], a1, v5.x); FMA_F32X2(vaA[3], a1, v5.y);
                FMA_F32X2(vaA[4], a1, v6.x); FMA_F32X2(vaA[5], a1, v6.y);
                FMA_F32X2(vaA[6], a1, v7.x); FMA_F32X2(vaA[7], a1, v7.y);
                FMA_F32X2(vaB[0], bp1, v4.x); FMA_F32X2(vaB[1], bp1, v4.y);
                FMA_F32X2(vaB[2], bp1, v5.x); FMA_F32X2(vaB[3], bp1, v5.y);
                FMA_F32X2(vaB[4], bp1, v6.x); FMA_F32X2(vaB[5], bp1, v6.y);
                FMA_F32X2(vaB[6], bp1, v7.x); FMA_F32X2(vaB[7], bp1, v7.y);
            }
        }
    }

    // ---- two-phase cross-slice reduction (red aliases x buffers) ----
    __syncthreads();   // all compute done everywhere

    if (s >= 8) {      // phase 1: upper slices spill 48 partials
        float* rp = red + ((s - 8) * 32 + t) * 49;
#pragma unroll
        for (int k = 0; k < 4; k++) UNPACK_F32X2(rp[2 * k],      rp[2 * k + 1],  gaA[k]);
#pragma unroll
        for (int k = 0; k < 8; k++) UNPACK_F32X2(rp[8 + 2 * k],  rp[9 + 2 * k],  vaA[k]);
#pragma unroll
        for (int k = 0; k < 4; k++) UNPACK_F32X2(rp[24 + 2 * k], rp[25 + 2 * k], gaB[k]);
#pragma unroll
        for (int k = 0; k < 8; k++) UNPACK_F32X2(rp[32 + 2 * k], rp[33 + 2 * k], vaB[k]);
    }
    __syncthreads();

    if (s < 8) {       // phase 2: lower slices combine own + paired upper
        float* rp = red + (s * 32 + t) * 49;
        float c[48];
#pragma unroll
        for (int k = 0; k < 4; k++) UNPACK_F32X2(c[2 * k],      c[2 * k + 1],  gaA[k]);
#pragma unroll
        for (int k = 0; k < 8; k++) UNPACK_F32X2(c[8 + 2 * k],  c[9 + 2 * k],  vaA[k]);
#pragma unroll
        for (int k = 0; k < 4; k++) UNPACK_F32X2(c[24 + 2 * k], c[25 + 2 * k], gaB[k]);
#pragma unroll
        for (int k = 0; k < 8; k++) UNPACK_F32X2(c[32 + 2 * k], c[33 + 2 * k], vaB[k]);
#pragma unroll
        for (int k = 0; k < 48; k++) c[k] += rp[k];
#pragma unroll
        for (int k = 0; k < 48; k++) rp[k] = c[k];
    }
    __syncthreads();

    if (tid < 64) {    // phase 3: final reduction over 8 slice-pairs per token
        const int q   = tid;            // token 0..63: m = q&3, brel = q>>2
        const int lt  = q & 31;
        const int off = (q >> 5) * 24;  // group A: cols 0..23, B: 24..47
        float acc[24];
#pragma unroll
        for (int k = 0; k < 24; k++) acc[k] = red[lt * 49 + off + k];
#pragma unroll
        for (int s2 = 1; s2 < 8; s2++) {
            const float* rp = red + (s2 * 32 + lt) * 49 + off;
#pragma unroll
            for (int k = 0; k < 24; k++) acc[k] += rp[k];
        }
        // gate logits (+bias); winner = max index among top-2 (ref semantics)
        float g[8];
#pragma unroll
        for (int e = 0; e < 8; e++) g[e] = acc[e] + gate_b[e];
        int i1 = 0; float m1 = g[0];
#pragma unroll
        for (int e = 1; e < 8; e++) if (g[e] > m1) { m1 = g[e]; i1 = e; }
        int i2 = 0; float m2 = -3.402823466e38f;
#pragma unroll
        for (int e = 0; e < 8; e++) if (e != i1 && g[e] > m2) { m2 = g[e]; i2 = e; }
        int w = (i1 > i2) ? i1 : i2;

        float o0 = acc[8 + (w << 1) + 0] + g_bdot[(w << 1) + 0];
        float o1 = acc[8 + (w << 1) + 1] + g_bdot[(w << 1) + 1];

        // modality mean: tokens q..q+3 share b, m = q&3 (consecutive lanes)
        o0 += __shfl_down_sync(0xffffffffu, o0, 2);
        o0 += __shfl_down_sync(0xffffffffu, o0, 1);
        o1 += __shfl_down_sync(0xffffffffu, o1, 2);
        o1 += __shfl_down_sync(0xffffffffu, o1, 1);

        if ((q & 3) == 0) {
            int b = b0 + (q >> 2);
            out[(b << 1) + 0] = 0.25f * o0 + head_b[0];
            out[(b << 1) + 1] = 0.25f * o1 + head_b[1];
        }
    }
}

// ---------------------------------------------------------------------------
extern "C" void kernel_launch(void* const* d_in, const int* in_sizes, int n_in,
                              void* d_out, int out_size)
{
    const float* x        = (const float*)d_in[0];
    const float* gate_w   = (const float*)d_in[1];
    const float* gate_b   = (const float*)d_in[2];
    const float* expert_w = (const float*)d_in[3];
    const float* expert_b = (const float*)d_in[4];
    const float* head_w   = (const float*)d_in[5];
    const float* head_b   = (const float*)d_in[6];
    float* out = (float*)d_out;

    const size_t SMEM = (24576 + 2 * 64 * XSTR) * sizeof(float);  // 164,864 B
    cudaFuncSetAttribute(moe_main_kernel,
                         cudaFuncAttributeMaxDynamicSharedMemorySize, (int)SMEM);

    build_vtab_kernel<<<1024, 256>>>(expert_w, head_w, expert_b);
    moe_main_kernel<<<128, 512, SMEM>>>(x, gate_w, gate_b, head_b, out);
}